// round 1
// baseline (speedup 1.0000x reference)
#include <cuda_runtime.h>

#define BB 2
#define NN 16384
#define CC 64
#define JJ 16
#define OO 128
#define TP 32
#define PSTR 36   // proj row stride in floats (padded; 144B, 16B-aligned)

// Transposed weight: [j][c][o], o contiguous -> coalesced epilogue loads.
__device__ float g_Wt[JJ * CC * OO];

__global__ void wt_transpose_kernel(const float* __restrict__ w) {
    int i = blockIdx.x * 256 + threadIdx.x;   // 131072 total
    int j = i >> 13;
    int c = (i >> 7) & 63;
    int o = i & 127;
    g_Wt[i] = w[(o * CC + c) * JJ + j];
}

__device__ __forceinline__ void ffma2(unsigned long long& a, unsigned long long x, unsigned long long y) {
    asm("fma.rn.f32x2 %0, %1, %2, %0;" : "+l"(a) : "l"(x), "l"(y));
}
__device__ __forceinline__ unsigned long long pk2(float lo, float hi) {
    unsigned long long r; asm("mov.b64 %0, {%1, %2};" : "=l"(r) : "f"(lo), "f"(hi)); return r;
}
__device__ __forceinline__ float2 up2(unsigned long long v) {
    float2 r; asm("mov.b64 {%0, %1}, %2;" : "=f"(r.x), "=f"(r.y) : "l"(v)); return r;
}

__global__ __launch_bounds__(128) void sconv_kernel(
    const float* __restrict__ x, const int* __restrict__ adj, float* __restrict__ out)
{
    __shared__ __align__(16) float xc[TP * CC];        // center points [p][c]
    __shared__ __align__(16) float proj[CC * PSTR];    // proj tile [c][p(+pad)]
    __shared__ int adjS[TP * JJ];                      // neighbor indices [p][j]

    int tid = threadIdx.x;
    int bx = blockIdx.x;
    int b  = bx >> 9;                 // 512 blocks per batch
    int n0 = (bx & 511) << 5;         // 32 points per block
    const float* xb = x + ((size_t)b * NN) * CC;

    // ---- preload center tile (2048 floats, coalesced float4) ----
    {
        const float4* src = (const float4*)(xb + n0 * CC);
        float4* dst = (float4*)xc;
        #pragma unroll
        for (int i = 0; i < 4; i++) dst[tid + 128 * i] = src[tid + 128 * i];
    }
    // ---- preload adjacency (skip self column 0) ----
    {
        int base = (b * NN + n0) * 17;
        #pragma unroll
        for (int i = 0; i < 4; i++) {
            int idx = tid + 128 * i;          // 512 ints
            int p = idx >> 4, jj = idx & 15;
            adjS[idx] = adj[base + p * 17 + 1 + jj];
        }
    }
    __syncthreads();

    const int ph = tid >> 6;            // point-half: 0 or 1 (16 points each)
    const int o0 = (tid & 63) << 1;     // 2 output channels per thread
    const int p_ = tid >> 2;            // stage-1: point id (4 lanes/point)
    const int l  = tid & 3;
    const int c0 = l << 4;              // stage-1: 16 channels per lane

    float m[32];
    #pragma unroll
    for (int i = 0; i < 32; i++) m[i] = 0.0f;   // relu+max -> init 0

    for (int j = 0; j < JJ; j++) {
        // ---- stage 1: gather neighbor, build proj[c][p] ----
        {
            int g = adjS[p_ * JJ + j];
            const float4* nb = (const float4*)(xb + g * CC) + (c0 >> 2);
            const float4* ce = (const float4*)(xc + p_ * CC + c0);
            float d[16];
            float ssq = 0.f;
            #pragma unroll
            for (int q = 0; q < 4; q++) {
                float4 nv = nb[q], cv = ce[q];
                d[4*q+0] = nv.x - cv.x; d[4*q+1] = nv.y - cv.y;
                d[4*q+2] = nv.z - cv.z; d[4*q+3] = nv.w - cv.w;
            }
            #pragma unroll
            for (int q = 0; q < 16; q++) ssq = fmaf(d[q], d[q], ssq);
            ssq += __shfl_xor_sync(0xffffffffu, ssq, 1);
            ssq += __shfl_xor_sync(0xffffffffu, ssq, 2);
            float s = rsqrtf(2.0f * ssq);   // 1/(sqrt2 * ||diff||)
            #pragma unroll
            for (int q = 0; q < 16; q++) proj[(c0 + q) * PSTR + p_] = d[q] * s;
        }
        __syncthreads();

        // ---- stage 2: 2x16 register tile of W_j @ proj^T, f32x2 packed ----
        unsigned long long acc[16];
        #pragma unroll
        for (int i = 0; i < 16; i++) acc[i] = 0ULL;

        const float2* Wj = (const float2*)(g_Wt + j * (CC * OO)) + (o0 >> 1);
        #pragma unroll 4
        for (int c = 0; c < CC; c++) {
            float2 w = Wj[c * 64];                       // coalesced LDG.64
            unsigned long long w0 = pk2(w.x, w.x);
            unsigned long long w1 = pk2(w.y, w.y);
            const ulonglong2* r = (const ulonglong2*)(proj + c * PSTR) + ph * 4;
            ulonglong2 u0 = r[0], u1 = r[1], u2 = r[2], u3 = r[3];  // broadcast LDS.128
            ffma2(acc[0],  w0, u0.x); ffma2(acc[1],  w0, u0.y);
            ffma2(acc[2],  w0, u1.x); ffma2(acc[3],  w0, u1.y);
            ffma2(acc[4],  w0, u2.x); ffma2(acc[5],  w0, u2.y);
            ffma2(acc[6],  w0, u3.x); ffma2(acc[7],  w0, u3.y);
            ffma2(acc[8],  w1, u0.x); ffma2(acc[9],  w1, u0.y);
            ffma2(acc[10], w1, u1.x); ffma2(acc[11], w1, u1.y);
            ffma2(acc[12], w1, u2.x); ffma2(acc[13], w1, u2.y);
            ffma2(acc[14], w1, u3.x); ffma2(acc[15], w1, u3.y);
        }
        #pragma unroll
        for (int i = 0; i < 16; i++) {
            float2 v = up2(acc[i]);
            int to = i >> 3, k = i & 7;
            m[to * 16 + 2 * k]     = fmaxf(m[to * 16 + 2 * k],     v.x);
            m[to * 16 + 2 * k + 1] = fmaxf(m[to * 16 + 2 * k + 1], v.y);
        }
        __syncthreads();   // protect proj before next j's stage 1
    }

    // ---- write out[b][o][n], 2 rows x 16 consecutive n per thread ----
    float* op = out + ((size_t)(b * OO + o0) * NN) + n0 + ph * 16;
    #pragma unroll
    for (int to = 0; to < 2; to++) {
        float4* v = (float4*)(op + (size_t)to * NN);
        #pragma unroll
        for (int q = 0; q < 4; q++)
            v[q] = make_float4(m[to*16 + 4*q], m[to*16 + 4*q + 1],
                               m[to*16 + 4*q + 2], m[to*16 + 4*q + 3]);
    }
}

extern "C" void kernel_launch(void* const* d_in, const int* in_sizes, int n_in,
                              void* d_out, int out_size) {
    const float* x   = (const float*)d_in[0];
    const int*   adj = (const int*)d_in[1];
    const float* w   = (const float*)d_in[2];
    float* out = (float*)d_out;

    wt_transpose_kernel<<<512, 256>>>(w);       // once per launch; trivial cost
    sconv_kernel<<<1024, 128>>>(x, adj, out);   // same stream -> ordered
}